// round 12
// baseline (speedup 1.0000x reference)
#include <cuda_runtime.h>
#include <math.h>

#define N_VOX (256*256*256)
#define NUM_SHELLS 222
#define NB (2*3*NUM_SHELLS)

// Hermitian-packed: 2 complex volumes (Z = X + iY per batch), two buffers.
// g_F : [batch][z][y][x]   (after pass 1)
// g_F2: [batch][y][z][x]   (after pass 2; z becomes the stride-256 axis)
__device__ float2 g_F [(size_t)2 * N_VOX];
__device__ float2 g_F2[(size_t)2 * N_VOX];
__device__ float  g_acc[NB];
__device__ float2 g_tw[256];   // W256^k

__constant__ float2 TW16C[8] = {
    { 1.0f,           0.0f          },
    { 0.92387953251f, -0.38268343236f },
    { 0.70710678119f, -0.70710678119f },
    { 0.38268343236f, -0.92387953251f },
    { 0.0f,          -1.0f          },
    {-0.38268343236f, -0.92387953251f },
    {-0.70710678119f, -0.70710678119f },
    {-0.92387953251f, -0.38268343236f }
};

__device__ __forceinline__ float2 cmulf(float2 a, float2 b) {
    return make_float2(a.x*b.x - a.y*b.y, a.x*b.y + a.y*b.x);
}

// 16-point radix-2 DIT FFT in registers. Natural in -> natural out.
__device__ __forceinline__ void fft16(float2 v[16]) {
    float2 t;
#define SWP(a,b) { t = v[a]; v[a] = v[b]; v[b] = t; }
    SWP(1,8) SWP(2,4) SWP(3,12) SWP(5,10) SWP(7,14) SWP(11,13)
#undef SWP
#pragma unroll
    for (int st = 0; st < 4; st++) {
        int half = 1 << st;
#pragma unroll
        for (int j = 0; j < 8; j++) {
            int pos = j & (half - 1);
            int i0  = ((j >> st) << (st + 1)) + pos;
            int i1  = i0 + half;
            float2 w = TW16C[pos << (3 - st)];
            float2 b = cmulf(w, v[i1]);
            float2 a = v[i0];
            v[i0] = make_float2(a.x + b.x, a.y + b.y);
            v[i1] = make_float2(a.x - b.x, a.y - b.y);
        }
    }
}

// ---------------------------------------------------------------------------
__global__ void init_kernel() {
    int tid = threadIdx.x;
    for (int i = tid; i < NB; i += blockDim.x) g_acc[i] = 0.0f;
    if (tid < 256) {
        float ang = -6.283185307179586f * (float)tid / 256.0f;
        float s, c;
        sincosf(ang, &s, &c);
        g_tw[tid] = make_float2(c, s);
    }
}

// ---------------------------------------------------------------------------
// Pass 1: x-FFT of Z = X + iY (one complex volume per batch).
// ---------------------------------------------------------------------------
__global__ void __launch_bounds__(256)
fft_x_kernel(const float* __restrict__ X, const float* __restrict__ Y) {
    __shared__ float2 sh[16][16][17];
    __shared__ float2 tws[256];
    int tid = threadIdx.x;
    tws[tid] = g_tw[tid];
    int tt = tid & 15;
    int l  = tid >> 4;
    int line = blockIdx.x * 16 + l;       // 0 .. 131071
    int vol  = line >> 16;                // batch 0/1
    int lin  = line & 65535;
    const float* sx = X + (size_t)vol * N_VOX + (size_t)lin * 256;
    const float* sy = Y + (size_t)vol * N_VOX + (size_t)lin * 256;

    float2 v[16];
#pragma unroll
    for (int i = 0; i < 16; i++)
        v[i] = make_float2(sx[tt + 16*i], sy[tt + 16*i]);
    fft16(v);
    __syncthreads();
#pragma unroll
    for (int k2 = 1; k2 < 16; k2++)
        v[k2] = cmulf(v[k2], tws[tt * k2]);
#pragma unroll
    for (int k2 = 0; k2 < 16; k2++)
        sh[l][tt][k2] = v[k2];
    __syncthreads();
    float2 u[16];
#pragma unroll
    for (int n1 = 0; n1 < 16; n1++)
        u[n1] = sh[l][n1][tt];
    fft16(u);
    float2* dst = g_F + (size_t)vol * N_VOX + (size_t)lin * 256;
#pragma unroll
    for (int k1 = 0; k1 < 16; k1++)
        dst[tt + 16*k1] = u[k1];
}

// ---------------------------------------------------------------------------
// Pass 2: y-FFT. Reads g_F [b][z][y][x] (stride-256 loads),
// writes g_F2 [b][y][z][x] (strided stores, fire-and-forget).
// ---------------------------------------------------------------------------
__global__ void __launch_bounds__(256)
fft_y_kernel() {
    __shared__ float2 sh[16][16][16];
    __shared__ float2 tws[256];
    int tid = threadIdx.x;
    tws[tid] = g_tw[tid];
    int c = tid & 15;
    int t = tid >> 4;
    int b    = blockIdx.x;
    int vol  = b >> 12;
    int rem  = b & 4095;
    int z    = rem >> 4;
    int tile = rem & 15;
    const float2* srcv = g_F  + (size_t)vol * N_VOX + (size_t)z * 65536 + tile * 16;
    float2*       dstv = g_F2 + (size_t)vol * N_VOX + (size_t)z * 256   + tile * 16;

    float2 v[16];
#pragma unroll
    for (int i = 0; i < 16; i++)
        v[i] = srcv[(size_t)(t + 16*i) * 256 + c];
    fft16(v);
    __syncthreads();
#pragma unroll
    for (int k2 = 1; k2 < 16; k2++)
        v[k2] = cmulf(v[k2], tws[t * k2]);
#pragma unroll
    for (int k2 = 0; k2 < 16; k2++)
        sh[t][k2][c] = v[k2];
    __syncthreads();
    float2 u[16];
#pragma unroll
    for (int n1 = 0; n1 < 16; n1++)
        u[n1] = sh[n1][t][c];
    fft16(u);
#pragma unroll
    for (int k1 = 0; k1 < 16; k1++)
        dstv[(size_t)(t + 16*k1) * 65536 + c] = u[k1];
}

// ---------------------------------------------------------------------------
// Pass 3: 1024 threads. Quarter q FFTs column set q of
// {(x,y), (xm,y), (x,ym), (xm,ym)} and publishes its z-spectrum to shared.
// Quarter 0 then bins full +/- orbits: 8 voxels (4 distinct values V1..V4,
// each Hermitian-weight-2-or-1) merged into ONE aggregated atomic head.
// Canonical cube x,y,z in 0..128. Block = (batch, y=0..128, x-tile of 16).
// Orbit-count coefficients (m* = 1 if coord in 1..127):
//   c1 = 1 + mx*my*mz   (V1 = f(x,y,z))
//   c2 = mx + my*mz     (V2 = f(xm,y,z))
//   c3 = my + mx*mz     (V3 = f(x,ym,z))
//   c4 = mz + mx*my     (V4 = f(xm,ym,z))
// Sum over cube of (c1+c2+c3+c4) = Prod(1+m) = 256^3 exactly.
// ---------------------------------------------------------------------------
#define SMEM_Z (4*4096*sizeof(float2) + 256*sizeof(float2) + 3*NUM_SHELLS*sizeof(float))

__device__ __forceinline__ void unpack3(float2 P, float2 Q,
                                        float& n, float& p, float& q_) {
    float xr = P.x + Q.x, xi = P.y - Q.y;   // 2*Fx
    float yr = P.y + Q.y, yi = Q.x - P.x;   // 2*Fy
    n  = xr*yr + xi*yi;
    p  = xr*xr + xi*xi;
    q_ = yr*yr + yi*yi;
}

__global__ void __launch_bounds__(1024, 1)
fft_z_reduce_kernel() {
    extern __shared__ unsigned char dynsm[];
    float2* shQ  = (float2*)dynsm;           // 4 buffers of 4096 float2
    float2* tws  = shQ + 4*4096;
    float*  bins = (float*)(tws + 256);

    int tid = threadIdx.x;
    if (tid < 256) tws[tid] = g_tw[tid];
    for (int i = tid; i < 3*NUM_SHELLS; i += 1024) bins[i] = 0.0f;

    int q  = tid >> 8;                   // quarter 0..3
    int wt = tid & 255;
    int c  = wt & 15;
    int t  = wt >> 4;
    int bI    = blockIdx.x;
    int batch = bI / 1161;               // 129*9
    int rem   = bI % 1161;
    int y     = rem / 9;                 // 0..128
    int tile  = rem % 9;                 // 0..8 (x = 0..143, masked > 128)
    int x  = tile * 16 + c;
    int xm = (256 - x) & 255;
    int ym = (256 - y) & 255;
    const float2* base = g_F2 + (size_t)batch * N_VOX;

    int colx = (q & 1) ? xm : x;
    int coly = (q & 2) ? ym : y;
    float2* mySh = shQ + q * 4096;

    float2 v[16];
#pragma unroll
    for (int i = 0; i < 16; i++)
        v[i] = base[(size_t)coly * 65536 + (size_t)(t + 16*i) * 256 + colx];
    fft16(v);
    __syncthreads();                     // #1: tws + bins ready
#pragma unroll
    for (int k2 = 1; k2 < 16; k2++)
        v[k2] = cmulf(v[k2], tws[t * k2]);
#pragma unroll
    for (int k2 = 0; k2 < 16; k2++)
        mySh[(t * 16 + k2) * 16 + c] = v[k2];
    __syncthreads();                     // #2: transpose ready
    float2 R[16];
#pragma unroll
    for (int n1 = 0; n1 < 16; n1++)
        R[n1] = mySh[(n1 * 16 + t) * 16 + c];
    fft16(R);                            // R[k1] = Fz(col, z = t + 16*k1)
    __syncthreads();                     // #3: transpose reads done
    // publish z-layout: mySh[z*16 + c] = Fz(col, z)
#pragma unroll
    for (int k1 = 0; k1 < 16; k1++)
        mySh[(t + 16*k1) * 16 + c] = R[k1];
    __syncthreads();                     // #4: all four z-layouts ready

    if (q == 0) {
        const float2* shA = shQ;
        const float2* shB = shQ + 4096;
        const float2* shC = shQ + 8192;
        const float2* shD = shQ + 12288;

        float vx   = (x <= 128) ? 1.0f : 0.0f;
        float mx   = ((unsigned)(x - 1) < 127u) ? 1.0f : 0.0f;
        float my   = ((unsigned)(y - 1) < 127u) ? 1.0f : 0.0f;
        float mxmy = mx * my;
        int fx = (x <= 128) ? x : 256 - x;   // keep bin in range for dead x
        int rxy = fx*fx + y*y;               // y canonical: fy = y

        const unsigned FULL = 0xffffffffu;
        int lpos = tid & 15;

#pragma unroll
        for (int k1 = 0; k1 < 8; k1++) {
            int z   = t + 16*k1;             // 0..127
            int zmw = (256 - z) & 255;       // partner plane (z=0 -> 0)
            float mz = (z >= 1) ? 1.0f : 0.0f;
            float c1 = vx * (1.0f + mxmy * mz);
            float c2 = vx * (mx + my * mz);
            float c3 = vx * (my + mx * mz);
            float c4 = vx * (mz + mxmy);

            int zi = z * 16 + c, zmi = zmw * 16 + c;
            float n1,p1,q1, n2,p2,q2, n3,p3,q3, n4,p4,q4;
            unpack3(shA[zi],  shD[zmi], n1, p1, q1);   // V1 = f(x,y,z)
            unpack3(shB[zi],  shC[zmi], n2, p2, q2);   // V2 = f(xm,y,z)
            unpack3(shC[zi],  shB[zmi], n3, p3, q3);   // V3 = f(x,ym,z)
            unpack3(shD[zi],  shA[zmi], n4, p4, q4);   // V4 = f(xm,ym,z)

            int bin = (int)sqrtf((float)(rxy + z*z));
            float nn = c1*n1 + c2*n2 + c3*n3 + c4*n4;
            float pp = c1*p1 + c2*p2 + c3*p3 + c4*p4;
            float qq = c1*q1 + c2*q2 + c3*q3 + c4*q4;

            // run-aggregation within each 16-lane segment (bin monotone in x)
#pragma unroll
            for (int off = 1; off < 16; off <<= 1) {
                int   ob = __shfl_down_sync(FULL, bin, off);
                float on = __shfl_down_sync(FULL, nn,  off);
                float op = __shfl_down_sync(FULL, pp,  off);
                float oq = __shfl_down_sync(FULL, qq,  off);
                if (lpos + off < 16 && ob == bin) { nn += on; pp += op; qq += oq; }
            }
            int pb = __shfl_up_sync(FULL, bin, 1);
            if (lpos == 0 || pb != bin) {
                atomicAdd(&bins[bin],                nn);
                atomicAdd(&bins[NUM_SHELLS   + bin], pp);
                atomicAdd(&bins[2*NUM_SHELLS + bin], qq);
            }
        }

        // z = 128 plane (self-partner): handled by t==0 lanes (warp 0).
        if (t == 0) {
            const unsigned M16 = 0x0000ffffu;
            int zi = 128 * 16 + c;
            float c1 = vx * 1.0f;
            float c2 = vx * mx;
            float c3 = vx * my;
            float c4 = vx * mxmy;
            float n1,p1,q1, n2,p2,q2, n3,p3,q3, n4,p4,q4;
            unpack3(shA[zi], shD[zi], n1, p1, q1);
            unpack3(shB[zi], shC[zi], n2, p2, q2);
            unpack3(shC[zi], shB[zi], n3, p3, q3);
            unpack3(shD[zi], shA[zi], n4, p4, q4);
            int bin = (int)sqrtf((float)(rxy + 16384));
            float nn = c1*n1 + c2*n2 + c3*n3 + c4*n4;
            float pp = c1*p1 + c2*p2 + c3*p3 + c4*p4;
            float qq = c1*q1 + c2*q2 + c3*q3 + c4*q4;
#pragma unroll
            for (int off = 1; off < 16; off <<= 1) {
                int   ob = __shfl_down_sync(M16, bin, off);
                float on = __shfl_down_sync(M16, nn,  off);
                float op = __shfl_down_sync(M16, pp,  off);
                float oq = __shfl_down_sync(M16, qq,  off);
                if (lpos + off < 16 && ob == bin) { nn += on; pp += op; qq += oq; }
            }
            int pb = __shfl_up_sync(M16, bin, 1);
            if (lpos == 0 || pb != bin) {
                atomicAdd(&bins[bin],                nn);
                atomicAdd(&bins[NUM_SHELLS   + bin], pp);
                atomicAdd(&bins[2*NUM_SHELLS + bin], qq);
            }
        }
    }
    __syncthreads();                     // #5: bins complete
    float* acc = g_acc + batch * 3 * NUM_SHELLS;
    for (int i = tid; i < 3 * NUM_SHELLS; i += 1024)
        atomicAdd(&acc[i], bins[i]);
}

// ---------------------------------------------------------------------------
__global__ void final_kernel(float* __restrict__ out) {
    __shared__ float red[256];
    int tid = threadIdx.x;
    float s = 0.0f;
    for (int i = tid; i < 2 * NUM_SHELLS; i += 256) {
        int bt = i / NUM_SHELLS;
        int sh_ = i % NUM_SHELLS;
        const float* acc = g_acc + bt * 3 * NUM_SHELLS;
        float num = acc[sh_];
        float px  = acc[NUM_SHELLS + sh_];
        float py  = acc[2*NUM_SHELLS + sh_];
        s += num / sqrtf(px * py + 1e-8f);
    }
    red[tid] = s;
    __syncthreads();
    for (int o = 128; o > 0; o >>= 1) {
        if (tid < o) red[tid] += red[tid + o];
        __syncthreads();
    }
    if (tid == 0) out[0] = red[0] / (2.0f * NUM_SHELLS);
}

// ---------------------------------------------------------------------------
extern "C" void kernel_launch(void* const* d_in, const int* in_sizes, int n_in,
                              void* d_out, int out_size) {
    const float* X = (const float*)d_in[0];
    const float* Y = (const float*)d_in[1];

    cudaFuncSetAttribute(fft_z_reduce_kernel,
                         cudaFuncAttributeMaxDynamicSharedMemorySize,
                         (int)SMEM_Z);

    init_kernel<<<1, 256>>>();
    fft_x_kernel<<<8192, 256>>>(X, Y);              // 2 vols * 65536 lines / 16
    fft_y_kernel<<<8192, 256>>>();                  // 2 vols * 256 z * 16 tiles
    fft_z_reduce_kernel<<<2322, 1024, SMEM_Z>>>();  // 2 * 129 y * 9 x-tiles
    final_kernel<<<1, 256>>>((float*)d_out);
}

// round 13
// speedup vs baseline: 1.0962x; 1.0962x over previous
#include <cuda_runtime.h>
#include <math.h>

#define N_VOX (256*256*256)
#define NUM_SHELLS 222
#define NB (2*3*NUM_SHELLS)

// Hermitian-packed: 2 complex volumes (Z = X + iY per batch), two buffers.
// g_F : [batch][z][y][x]   (after pass 1)
// g_F2: [batch][y][z][x]   (after pass 2; z becomes the stride-256 axis)
__device__ float2 g_F [(size_t)2 * N_VOX];
__device__ float2 g_F2[(size_t)2 * N_VOX];
__device__ float  g_acc[NB];
__device__ float2 g_tw[256];   // W256^k

__constant__ float2 TW16C[8] = {
    { 1.0f,           0.0f          },
    { 0.92387953251f, -0.38268343236f },
    { 0.70710678119f, -0.70710678119f },
    { 0.38268343236f, -0.92387953251f },
    { 0.0f,          -1.0f          },
    {-0.38268343236f, -0.92387953251f },
    {-0.70710678119f, -0.70710678119f },
    {-0.92387953251f, -0.38268343236f }
};

__device__ __forceinline__ float2 cmulf(float2 a, float2 b) {
    return make_float2(a.x*b.x - a.y*b.y, a.x*b.y + a.y*b.x);
}

// 16-point radix-2 DIT FFT in registers. Natural in -> natural out.
__device__ __forceinline__ void fft16(float2 v[16]) {
    float2 t;
#define SWP(a,b) { t = v[a]; v[a] = v[b]; v[b] = t; }
    SWP(1,8) SWP(2,4) SWP(3,12) SWP(5,10) SWP(7,14) SWP(11,13)
#undef SWP
#pragma unroll
    for (int st = 0; st < 4; st++) {
        int half = 1 << st;
#pragma unroll
        for (int j = 0; j < 8; j++) {
            int pos = j & (half - 1);
            int i0  = ((j >> st) << (st + 1)) + pos;
            int i1  = i0 + half;
            float2 w = TW16C[pos << (3 - st)];
            float2 b = cmulf(w, v[i1]);
            float2 a = v[i0];
            v[i0] = make_float2(a.x + b.x, a.y + b.y);
            v[i1] = make_float2(a.x - b.x, a.y - b.y);
        }
    }
}

// ---------------------------------------------------------------------------
__global__ void init_kernel() {
    int tid = threadIdx.x;
    for (int i = tid; i < NB; i += blockDim.x) g_acc[i] = 0.0f;
    if (tid < 256) {
        float ang = -6.283185307179586f * (float)tid / 256.0f;
        float s, c;
        sincosf(ang, &s, &c);
        g_tw[tid] = make_float2(c, s);
    }
}

// ---------------------------------------------------------------------------
// Pass 1: x-FFT of Z = X + iY (one complex volume per batch).
// ---------------------------------------------------------------------------
__global__ void __launch_bounds__(256)
fft_x_kernel(const float* __restrict__ X, const float* __restrict__ Y) {
    __shared__ float2 sh[16][16][17];
    __shared__ float2 tws[256];
    int tid = threadIdx.x;
    tws[tid] = g_tw[tid];
    int tt = tid & 15;
    int l  = tid >> 4;
    int line = blockIdx.x * 16 + l;       // 0 .. 131071
    int vol  = line >> 16;                // batch 0/1
    int lin  = line & 65535;
    const float* sx = X + (size_t)vol * N_VOX + (size_t)lin * 256;
    const float* sy = Y + (size_t)vol * N_VOX + (size_t)lin * 256;

    float2 v[16];
#pragma unroll
    for (int i = 0; i < 16; i++)
        v[i] = make_float2(sx[tt + 16*i], sy[tt + 16*i]);
    fft16(v);
    __syncthreads();
#pragma unroll
    for (int k2 = 1; k2 < 16; k2++)
        v[k2] = cmulf(v[k2], tws[tt * k2]);
#pragma unroll
    for (int k2 = 0; k2 < 16; k2++)
        sh[l][tt][k2] = v[k2];
    __syncthreads();
    float2 u[16];
#pragma unroll
    for (int n1 = 0; n1 < 16; n1++)
        u[n1] = sh[l][n1][tt];
    fft16(u);
    float2* dst = g_F + (size_t)vol * N_VOX + (size_t)lin * 256;
#pragma unroll
    for (int k1 = 0; k1 < 16; k1++)
        dst[tt + 16*k1] = u[k1];
}

// ---------------------------------------------------------------------------
// Pass 2: y-FFT. Reads g_F [b][z][y][x] (stride-256 loads),
// writes g_F2 [b][y][z][x] (strided stores, fire-and-forget).
// ---------------------------------------------------------------------------
__global__ void __launch_bounds__(256)
fft_y_kernel() {
    __shared__ float2 sh[16][16][16];
    __shared__ float2 tws[256];
    int tid = threadIdx.x;
    tws[tid] = g_tw[tid];
    int c = tid & 15;
    int t = tid >> 4;
    int b    = blockIdx.x;
    int vol  = b >> 12;
    int rem  = b & 4095;
    int z    = rem >> 4;
    int tile = rem & 15;
    const float2* srcv = g_F  + (size_t)vol * N_VOX + (size_t)z * 65536 + tile * 16;
    float2*       dstv = g_F2 + (size_t)vol * N_VOX + (size_t)z * 256   + tile * 16;

    float2 v[16];
#pragma unroll
    for (int i = 0; i < 16; i++)
        v[i] = srcv[(size_t)(t + 16*i) * 256 + c];
    fft16(v);
    __syncthreads();
#pragma unroll
    for (int k2 = 1; k2 < 16; k2++)
        v[k2] = cmulf(v[k2], tws[t * k2]);
#pragma unroll
    for (int k2 = 0; k2 < 16; k2++)
        sh[t][k2][c] = v[k2];
    __syncthreads();
    float2 u[16];
#pragma unroll
    for (int n1 = 0; n1 < 16; n1++)
        u[n1] = sh[n1][t][c];
    fft16(u);
#pragma unroll
    for (int k1 = 0; k1 < 16; k1++)
        dstv[(size_t)(t + 16*k1) * 65536 + c] = u[k1];
}

// ---------------------------------------------------------------------------
// Pass 3: 1024 threads. Quarter q FFTs column set q of
// {(x,y), (xm,y), (x,ym), (xm,ym)} and publishes its z-spectrum to shared.
// Then ALL quarters bin full +/- orbits — quarter q takes k1 in {2q, 2q+1}
// (8 voxels per orbit, merged in registers into ONE aggregated atomic head).
// Canonical cube x,y,z in 0..128. Block = (batch, y=0..128, x-tile of 16).
// Orbit-count coefficients (m* = 1 if coord in 1..127):
//   c1 = 1 + mx*my*mz   (V1 = f(x,y,z))
//   c2 = mx + my*mz     (V2 = f(xm,y,z))
//   c3 = my + mx*mz     (V3 = f(x,ym,z))
//   c4 = mz + mx*my     (V4 = f(xm,ym,z))
// Sum over cube of (c1+c2+c3+c4) = Prod(1+m) = 256^3 exactly.
// ---------------------------------------------------------------------------
#define SMEM_Z (4*4096*sizeof(float2) + 256*sizeof(float2) + 3*NUM_SHELLS*sizeof(float))

__device__ __forceinline__ void unpack3(float2 P, float2 Q,
                                        float& n, float& p, float& q_) {
    float xr = P.x + Q.x, xi = P.y - Q.y;   // 2*Fx
    float yr = P.y + Q.y, yi = Q.x - P.x;   // 2*Fy
    n  = xr*yr + xi*yi;
    p  = xr*xr + xi*xi;
    q_ = yr*yr + yi*yi;
}

__global__ void __launch_bounds__(1024, 1)
fft_z_reduce_kernel() {
    extern __shared__ unsigned char dynsm[];
    float2* shQ  = (float2*)dynsm;           // 4 buffers of 4096 float2
    float2* tws  = shQ + 4*4096;
    float*  bins = (float*)(tws + 256);

    int tid = threadIdx.x;
    if (tid < 256) tws[tid] = g_tw[tid];
    for (int i = tid; i < 3*NUM_SHELLS; i += 1024) bins[i] = 0.0f;

    int q  = tid >> 8;                   // quarter 0..3
    int wt = tid & 255;
    int c  = wt & 15;
    int t  = wt >> 4;
    int bI    = blockIdx.x;
    int batch = bI / 1161;               // 129*9
    int rem   = bI % 1161;
    int y     = rem / 9;                 // 0..128
    int tile  = rem % 9;                 // 0..8 (x = 0..143, masked > 128)
    int x  = tile * 16 + c;
    int xm = (256 - x) & 255;
    int ym = (256 - y) & 255;
    const float2* base = g_F2 + (size_t)batch * N_VOX;

    int colx = (q & 1) ? xm : x;
    int coly = (q & 2) ? ym : y;
    float2* mySh = shQ + q * 4096;

    float2 v[16];
#pragma unroll
    for (int i = 0; i < 16; i++)
        v[i] = base[(size_t)coly * 65536 + (size_t)(t + 16*i) * 256 + colx];
    fft16(v);
    __syncthreads();                     // #1: tws + bins ready
#pragma unroll
    for (int k2 = 1; k2 < 16; k2++)
        v[k2] = cmulf(v[k2], tws[t * k2]);
#pragma unroll
    for (int k2 = 0; k2 < 16; k2++)
        mySh[(t * 16 + k2) * 16 + c] = v[k2];
    __syncthreads();                     // #2: transpose ready
    float2 R[16];
#pragma unroll
    for (int n1 = 0; n1 < 16; n1++)
        R[n1] = mySh[(n1 * 16 + t) * 16 + c];
    fft16(R);                            // R[k1] = Fz(col, z = t + 16*k1)
    __syncthreads();                     // #3: transpose reads done
    // publish z-layout: mySh[z*16 + c] = Fz(col, z)
#pragma unroll
    for (int k1 = 0; k1 < 16; k1++)
        mySh[(t + 16*k1) * 16 + c] = R[k1];
    __syncthreads();                     // #4: all four z-layouts ready

    // ---- orbit binning: ALL quarters participate; quarter q takes
    //      k1 = 2q + j, j in {0,1}. Reads only shared z-layouts. ----
    {
        const float2* shA = shQ;
        const float2* shB = shQ + 4096;
        const float2* shC = shQ + 8192;
        const float2* shD = shQ + 12288;

        float vx   = (x <= 128) ? 1.0f : 0.0f;
        float mx   = ((unsigned)(x - 1) < 127u) ? 1.0f : 0.0f;
        float my   = ((unsigned)(y - 1) < 127u) ? 1.0f : 0.0f;
        float mxmy = mx * my;
        int fx = (x <= 128) ? x : 256 - x;   // keep bin in range for dead x
        int rxy = fx*fx + y*y;               // y canonical: fy = y

        const unsigned FULL = 0xffffffffu;
        int lpos = tid & 15;

#pragma unroll
        for (int j = 0; j < 2; j++) {
            int k1  = 2*q + j;
            int z   = t + 16*k1;             // 0..127 (covered once across quarters)
            int zmw = (256 - z) & 255;       // partner plane (z=0 -> 0)
            float mz = (z >= 1) ? 1.0f : 0.0f;
            float c1 = vx * (1.0f + mxmy * mz);
            float c2 = vx * (mx + my * mz);
            float c3 = vx * (my + mx * mz);
            float c4 = vx * (mz + mxmy);

            int zi = z * 16 + c, zmi = zmw * 16 + c;
            float n1,p1,q1, n2,p2,q2, n3,p3,q3, n4,p4,q4;
            unpack3(shA[zi],  shD[zmi], n1, p1, q1);   // V1 = f(x,y,z)
            unpack3(shB[zi],  shC[zmi], n2, p2, q2);   // V2 = f(xm,y,z)
            unpack3(shC[zi],  shB[zmi], n3, p3, q3);   // V3 = f(x,ym,z)
            unpack3(shD[zi],  shA[zmi], n4, p4, q4);   // V4 = f(xm,ym,z)

            int bin = (int)sqrtf((float)(rxy + z*z));
            float nn = c1*n1 + c2*n2 + c3*n3 + c4*n4;
            float pp = c1*p1 + c2*p2 + c3*p3 + c4*p4;
            float qq = c1*q1 + c2*q2 + c3*q3 + c4*q4;

            // run-aggregation within each 16-lane segment (bin monotone in x)
#pragma unroll
            for (int off = 1; off < 16; off <<= 1) {
                int   ob = __shfl_down_sync(FULL, bin, off);
                float on = __shfl_down_sync(FULL, nn,  off);
                float op = __shfl_down_sync(FULL, pp,  off);
                float oq = __shfl_down_sync(FULL, qq,  off);
                if (lpos + off < 16 && ob == bin) { nn += on; pp += op; qq += oq; }
            }
            int pb = __shfl_up_sync(FULL, bin, 1);
            if (lpos == 0 || pb != bin) {
                atomicAdd(&bins[bin],                nn);
                atomicAdd(&bins[NUM_SHELLS   + bin], pp);
                atomicAdd(&bins[2*NUM_SHELLS + bin], qq);
            }
        }

        // z = 128 plane (self-partner): quarter 0, t==0 segment only.
        if (q == 0 && t == 0) {
            const unsigned M16 = 0x0000ffffu;
            int zi = 128 * 16 + c;
            float c1 = vx * 1.0f;
            float c2 = vx * mx;
            float c3 = vx * my;
            float c4 = vx * mxmy;
            float n1,p1,q1, n2,p2,q2, n3,p3,q3, n4,p4,q4;
            unpack3(shA[zi], shD[zi], n1, p1, q1);
            unpack3(shB[zi], shC[zi], n2, p2, q2);
            unpack3(shC[zi], shB[zi], n3, p3, q3);
            unpack3(shD[zi], shA[zi], n4, p4, q4);
            int bin = (int)sqrtf((float)(rxy + 16384));
            float nn = c1*n1 + c2*n2 + c3*n3 + c4*n4;
            float pp = c1*p1 + c2*p2 + c3*p3 + c4*p4;
            float qq = c1*q1 + c2*q2 + c3*q3 + c4*q4;
#pragma unroll
            for (int off = 1; off < 16; off <<= 1) {
                int   ob = __shfl_down_sync(M16, bin, off);
                float on = __shfl_down_sync(M16, nn,  off);
                float op = __shfl_down_sync(M16, pp,  off);
                float oq = __shfl_down_sync(M16, qq,  off);
                if (lpos + off < 16 && ob == bin) { nn += on; pp += op; qq += oq; }
            }
            int pb = __shfl_up_sync(M16, bin, 1);
            if (lpos == 0 || pb != bin) {
                atomicAdd(&bins[bin],                nn);
                atomicAdd(&bins[NUM_SHELLS   + bin], pp);
                atomicAdd(&bins[2*NUM_SHELLS + bin], qq);
            }
        }
    }
    __syncthreads();                     // #5: bins complete
    float* acc = g_acc + batch * 3 * NUM_SHELLS;
    for (int i = tid; i < 3 * NUM_SHELLS; i += 1024)
        atomicAdd(&acc[i], bins[i]);
}

// ---------------------------------------------------------------------------
__global__ void final_kernel(float* __restrict__ out) {
    __shared__ float red[256];
    int tid = threadIdx.x;
    float s = 0.0f;
    for (int i = tid; i < 2 * NUM_SHELLS; i += 256) {
        int bt = i / NUM_SHELLS;
        int sh_ = i % NUM_SHELLS;
        const float* acc = g_acc + bt * 3 * NUM_SHELLS;
        float num = acc[sh_];
        float px  = acc[NUM_SHELLS + sh_];
        float py  = acc[2*NUM_SHELLS + sh_];
        s += num / sqrtf(px * py + 1e-8f);
    }
    red[tid] = s;
    __syncthreads();
    for (int o = 128; o > 0; o >>= 1) {
        if (tid < o) red[tid] += red[tid + o];
        __syncthreads();
    }
    if (tid == 0) out[0] = red[0] / (2.0f * NUM_SHELLS);
}

// ---------------------------------------------------------------------------
extern "C" void kernel_launch(void* const* d_in, const int* in_sizes, int n_in,
                              void* d_out, int out_size) {
    const float* X = (const float*)d_in[0];
    const float* Y = (const float*)d_in[1];

    cudaFuncSetAttribute(fft_z_reduce_kernel,
                         cudaFuncAttributeMaxDynamicSharedMemorySize,
                         (int)SMEM_Z);

    init_kernel<<<1, 256>>>();
    fft_x_kernel<<<8192, 256>>>(X, Y);              // 2 vols * 65536 lines / 16
    fft_y_kernel<<<8192, 256>>>();                  // 2 vols * 256 z * 16 tiles
    fft_z_reduce_kernel<<<2322, 1024, SMEM_Z>>>();  // 2 * 129 y * 9 x-tiles
    final_kernel<<<1, 256>>>((float*)d_out);
}

// round 14
// speedup vs baseline: 1.2442x; 1.1350x over previous
#include <cuda_runtime.h>
#include <cuda_fp16.h>
#include <math.h>

#define N_VOX (256*256*256)
#define NUM_SHELLS 222
#define NB (2*3*NUM_SHELLS)

// Hermitian-packed: 2 complex volumes (Z = X + iY per batch), two buffers,
// stored as half2 (re,im) — fp16 round-off is ~2e-4 relative, FSC is a
// normalized correlation so the final scalar error stays ~1e-5.
// g_F : [batch][z][y][x]   (after pass 1)
// g_F2: [batch][y][z][x]   (after pass 2; z becomes the stride-256 axis)
__device__ __half2 g_F [(size_t)2 * N_VOX];
__device__ __half2 g_F2[(size_t)2 * N_VOX];
__device__ float   g_acc[NB];
__device__ float2  g_tw[256];   // W256^k

__constant__ float2 TW16C[8] = {
    { 1.0f,           0.0f          },
    { 0.92387953251f, -0.38268343236f },
    { 0.70710678119f, -0.70710678119f },
    { 0.38268343236f, -0.92387953251f },
    { 0.0f,          -1.0f          },
    {-0.38268343236f, -0.92387953251f },
    {-0.70710678119f, -0.70710678119f },
    {-0.92387953251f, -0.38268343236f }
};

__device__ __forceinline__ float2 cmulf(float2 a, float2 b) {
    return make_float2(a.x*b.x - a.y*b.y, a.x*b.y + a.y*b.x);
}

__device__ __forceinline__ __half2 f2h(float2 a) {
    return __floats2half2_rn(a.x, a.y);
}
__device__ __forceinline__ float2 h2f(__half2 a) {
    return __half22float2(a);
}

// 16-point radix-2 DIT FFT in registers. Natural in -> natural out.
__device__ __forceinline__ void fft16(float2 v[16]) {
    float2 t;
#define SWP(a,b) { t = v[a]; v[a] = v[b]; v[b] = t; }
    SWP(1,8) SWP(2,4) SWP(3,12) SWP(5,10) SWP(7,14) SWP(11,13)
#undef SWP
#pragma unroll
    for (int st = 0; st < 4; st++) {
        int half = 1 << st;
#pragma unroll
        for (int j = 0; j < 8; j++) {
            int pos = j & (half - 1);
            int i0  = ((j >> st) << (st + 1)) + pos;
            int i1  = i0 + half;
            float2 w = TW16C[pos << (3 - st)];
            float2 b = cmulf(w, v[i1]);
            float2 a = v[i0];
            v[i0] = make_float2(a.x + b.x, a.y + b.y);
            v[i1] = make_float2(a.x - b.x, a.y - b.y);
        }
    }
}

// ---------------------------------------------------------------------------
__global__ void init_kernel() {
    int tid = threadIdx.x;
    for (int i = tid; i < NB; i += blockDim.x) g_acc[i] = 0.0f;
    if (tid < 256) {
        float ang = -6.283185307179586f * (float)tid / 256.0f;
        float s, c;
        sincosf(ang, &s, &c);
        g_tw[tid] = make_float2(c, s);
    }
}

// ---------------------------------------------------------------------------
// Pass 1: x-FFT of Z = X + iY (one complex volume per batch). fp32 in, fp16 out.
// ---------------------------------------------------------------------------
__global__ void __launch_bounds__(256)
fft_x_kernel(const float* __restrict__ X, const float* __restrict__ Y) {
    __shared__ float2 sh[16][16][17];
    __shared__ float2 tws[256];
    int tid = threadIdx.x;
    tws[tid] = g_tw[tid];
    int tt = tid & 15;
    int l  = tid >> 4;
    int line = blockIdx.x * 16 + l;       // 0 .. 131071
    int vol  = line >> 16;                // batch 0/1
    int lin  = line & 65535;
    const float* sx = X + (size_t)vol * N_VOX + (size_t)lin * 256;
    const float* sy = Y + (size_t)vol * N_VOX + (size_t)lin * 256;

    float2 v[16];
#pragma unroll
    for (int i = 0; i < 16; i++)
        v[i] = make_float2(sx[tt + 16*i], sy[tt + 16*i]);
    fft16(v);
    __syncthreads();
#pragma unroll
    for (int k2 = 1; k2 < 16; k2++)
        v[k2] = cmulf(v[k2], tws[tt * k2]);
#pragma unroll
    for (int k2 = 0; k2 < 16; k2++)
        sh[l][tt][k2] = v[k2];
    __syncthreads();
    float2 u[16];
#pragma unroll
    for (int n1 = 0; n1 < 16; n1++)
        u[n1] = sh[l][n1][tt];
    fft16(u);
    __half2* dst = g_F + (size_t)vol * N_VOX + (size_t)lin * 256;
#pragma unroll
    for (int k1 = 0; k1 < 16; k1++)
        dst[tt + 16*k1] = f2h(u[k1]);
}

// ---------------------------------------------------------------------------
// Pass 2: y-FFT. Reads g_F [b][z][y][x] (stride-256 loads, half2),
// writes g_F2 [b][y][z][x] (strided stores, half2, fire-and-forget).
// ---------------------------------------------------------------------------
__global__ void __launch_bounds__(256)
fft_y_kernel() {
    __shared__ float2 sh[16][16][16];
    __shared__ float2 tws[256];
    int tid = threadIdx.x;
    tws[tid] = g_tw[tid];
    int c = tid & 15;
    int t = tid >> 4;
    int b    = blockIdx.x;
    int vol  = b >> 12;
    int rem  = b & 4095;
    int z    = rem >> 4;
    int tile = rem & 15;
    const __half2* srcv = g_F  + (size_t)vol * N_VOX + (size_t)z * 65536 + tile * 16;
    __half2*       dstv = g_F2 + (size_t)vol * N_VOX + (size_t)z * 256   + tile * 16;

    float2 v[16];
#pragma unroll
    for (int i = 0; i < 16; i++)
        v[i] = h2f(srcv[(size_t)(t + 16*i) * 256 + c]);
    fft16(v);
    __syncthreads();
#pragma unroll
    for (int k2 = 1; k2 < 16; k2++)
        v[k2] = cmulf(v[k2], tws[t * k2]);
#pragma unroll
    for (int k2 = 0; k2 < 16; k2++)
        sh[t][k2][c] = v[k2];
    __syncthreads();
    float2 u[16];
#pragma unroll
    for (int n1 = 0; n1 < 16; n1++)
        u[n1] = sh[n1][t][c];
    fft16(u);
#pragma unroll
    for (int k1 = 0; k1 < 16; k1++)
        dstv[(size_t)(t + 16*k1) * 65536 + c] = f2h(u[k1]);
}

// ---------------------------------------------------------------------------
// Pass 3: 1024 threads. Quarter q FFTs column set q of
// {(x,y), (xm,y), (x,ym), (xm,ym)} and publishes its z-spectrum to shared.
// Then ALL quarters bin full +/- orbits — quarter q takes k1 in {2q, 2q+1}
// (8 voxels per orbit, merged in registers into ONE aggregated atomic head).
// Canonical cube x,y,z in 0..128. Block = (batch, y=0..128, x-tile of 16).
// Orbit-count coefficients (m* = 1 if coord in 1..127):
//   c1 = 1 + mx*my*mz   (V1 = f(x,y,z))
//   c2 = mx + my*mz     (V2 = f(xm,y,z))
//   c3 = my + mx*mz     (V3 = f(x,ym,z))
//   c4 = mz + mx*my     (V4 = f(xm,ym,z))
// Sum over cube of (c1+c2+c3+c4) = Prod(1+m) = 256^3 exactly.
// ---------------------------------------------------------------------------
#define SMEM_Z (4*4096*sizeof(float2) + 256*sizeof(float2) + 3*NUM_SHELLS*sizeof(float))

__device__ __forceinline__ void unpack3(float2 P, float2 Q,
                                        float& n, float& p, float& q_) {
    float xr = P.x + Q.x, xi = P.y - Q.y;   // 2*Fx
    float yr = P.y + Q.y, yi = Q.x - P.x;   // 2*Fy
    n  = xr*yr + xi*yi;
    p  = xr*xr + xi*xi;
    q_ = yr*yr + yi*yi;
}

__global__ void __launch_bounds__(1024, 1)
fft_z_reduce_kernel() {
    extern __shared__ unsigned char dynsm[];
    float2* shQ  = (float2*)dynsm;           // 4 buffers of 4096 float2
    float2* tws  = shQ + 4*4096;
    float*  bins = (float*)(tws + 256);

    int tid = threadIdx.x;
    if (tid < 256) tws[tid] = g_tw[tid];
    for (int i = tid; i < 3*NUM_SHELLS; i += 1024) bins[i] = 0.0f;

    int q  = tid >> 8;                   // quarter 0..3
    int wt = tid & 255;
    int c  = wt & 15;
    int t  = wt >> 4;
    int bI    = blockIdx.x;
    int batch = bI / 1161;               // 129*9
    int rem   = bI % 1161;
    int y     = rem / 9;                 // 0..128
    int tile  = rem % 9;                 // 0..8 (x = 0..143, masked > 128)
    int x  = tile * 16 + c;
    int xm = (256 - x) & 255;
    int ym = (256 - y) & 255;
    const __half2* base = g_F2 + (size_t)batch * N_VOX;

    int colx = (q & 1) ? xm : x;
    int coly = (q & 2) ? ym : y;
    float2* mySh = shQ + q * 4096;

    float2 v[16];
#pragma unroll
    for (int i = 0; i < 16; i++)
        v[i] = h2f(base[(size_t)coly * 65536 + (size_t)(t + 16*i) * 256 + colx]);
    fft16(v);
    __syncthreads();                     // #1: tws + bins ready
#pragma unroll
    for (int k2 = 1; k2 < 16; k2++)
        v[k2] = cmulf(v[k2], tws[t * k2]);
#pragma unroll
    for (int k2 = 0; k2 < 16; k2++)
        mySh[(t * 16 + k2) * 16 + c] = v[k2];
    __syncthreads();                     // #2: transpose ready
    float2 R[16];
#pragma unroll
    for (int n1 = 0; n1 < 16; n1++)
        R[n1] = mySh[(n1 * 16 + t) * 16 + c];
    fft16(R);                            // R[k1] = Fz(col, z = t + 16*k1)
    __syncthreads();                     // #3: transpose reads done
    // publish z-layout: mySh[z*16 + c] = Fz(col, z)
#pragma unroll
    for (int k1 = 0; k1 < 16; k1++)
        mySh[(t + 16*k1) * 16 + c] = R[k1];
    __syncthreads();                     // #4: all four z-layouts ready

    // ---- orbit binning: ALL quarters participate; quarter q takes
    //      k1 = 2q + j, j in {0,1}. Reads only shared z-layouts. ----
    {
        const float2* shA = shQ;
        const float2* shB = shQ + 4096;
        const float2* shC = shQ + 8192;
        const float2* shD = shQ + 12288;

        float vx   = (x <= 128) ? 1.0f : 0.0f;
        float mx   = ((unsigned)(x - 1) < 127u) ? 1.0f : 0.0f;
        float my   = ((unsigned)(y - 1) < 127u) ? 1.0f : 0.0f;
        float mxmy = mx * my;
        int fx = (x <= 128) ? x : 256 - x;   // keep bin in range for dead x
        int rxy = fx*fx + y*y;               // y canonical: fy = y

        const unsigned FULL = 0xffffffffu;
        int lpos = tid & 15;

#pragma unroll
        for (int j = 0; j < 2; j++) {
            int k1  = 2*q + j;
            int z   = t + 16*k1;             // 0..127 (covered once across quarters)
            int zmw = (256 - z) & 255;       // partner plane (z=0 -> 0)
            float mz = (z >= 1) ? 1.0f : 0.0f;
            float c1 = vx * (1.0f + mxmy * mz);
            float c2 = vx * (mx + my * mz);
            float c3 = vx * (my + mx * mz);
            float c4 = vx * (mz + mxmy);

            int zi = z * 16 + c, zmi = zmw * 16 + c;
            float n1,p1,q1, n2,p2,q2, n3,p3,q3, n4,p4,q4;
            unpack3(shA[zi],  shD[zmi], n1, p1, q1);   // V1 = f(x,y,z)
            unpack3(shB[zi],  shC[zmi], n2, p2, q2);   // V2 = f(xm,y,z)
            unpack3(shC[zi],  shB[zmi], n3, p3, q3);   // V3 = f(x,ym,z)
            unpack3(shD[zi],  shA[zmi], n4, p4, q4);   // V4 = f(xm,ym,z)

            int bin = (int)sqrtf((float)(rxy + z*z));
            float nn = c1*n1 + c2*n2 + c3*n3 + c4*n4;
            float pp = c1*p1 + c2*p2 + c3*p3 + c4*p4;
            float qq = c1*q1 + c2*q2 + c3*q3 + c4*q4;

            // run-aggregation within each 16-lane segment (bin monotone in x)
#pragma unroll
            for (int off = 1; off < 16; off <<= 1) {
                int   ob = __shfl_down_sync(FULL, bin, off);
                float on = __shfl_down_sync(FULL, nn,  off);
                float op = __shfl_down_sync(FULL, pp,  off);
                float oq = __shfl_down_sync(FULL, qq,  off);
                if (lpos + off < 16 && ob == bin) { nn += on; pp += op; qq += oq; }
            }
            int pb = __shfl_up_sync(FULL, bin, 1);
            if (lpos == 0 || pb != bin) {
                atomicAdd(&bins[bin],                nn);
                atomicAdd(&bins[NUM_SHELLS   + bin], pp);
                atomicAdd(&bins[2*NUM_SHELLS + bin], qq);
            }
        }

        // z = 128 plane (self-partner): quarter 0, t==0 segment only.
        if (q == 0 && t == 0) {
            const unsigned M16 = 0x0000ffffu;
            int zi = 128 * 16 + c;
            float c1 = vx * 1.0f;
            float c2 = vx * mx;
            float c3 = vx * my;
            float c4 = vx * mxmy;
            float n1,p1,q1, n2,p2,q2, n3,p3,q3, n4,p4,q4;
            unpack3(shA[zi], shD[zi], n1, p1, q1);
            unpack3(shB[zi], shC[zi], n2, p2, q2);
            unpack3(shC[zi], shB[zi], n3, p3, q3);
            unpack3(shD[zi], shA[zi], n4, p4, q4);
            int bin = (int)sqrtf((float)(rxy + 16384));
            float nn = c1*n1 + c2*n2 + c3*n3 + c4*n4;
            float pp = c1*p1 + c2*p2 + c3*p3 + c4*p4;
            float qq = c1*q1 + c2*q2 + c3*q3 + c4*q4;
#pragma unroll
            for (int off = 1; off < 16; off <<= 1) {
                int   ob = __shfl_down_sync(M16, bin, off);
                float on = __shfl_down_sync(M16, nn,  off);
                float op = __shfl_down_sync(M16, pp,  off);
                float oq = __shfl_down_sync(M16, qq,  off);
                if (lpos + off < 16 && ob == bin) { nn += on; pp += op; qq += oq; }
            }
            int pb = __shfl_up_sync(M16, bin, 1);
            if (lpos == 0 || pb != bin) {
                atomicAdd(&bins[bin],                nn);
                atomicAdd(&bins[NUM_SHELLS   + bin], pp);
                atomicAdd(&bins[2*NUM_SHELLS + bin], qq);
            }
        }
    }
    __syncthreads();                     // #5: bins complete
    float* acc = g_acc + batch * 3 * NUM_SHELLS;
    for (int i = tid; i < 3 * NUM_SHELLS; i += 1024)
        atomicAdd(&acc[i], bins[i]);
}

// ---------------------------------------------------------------------------
__global__ void final_kernel(float* __restrict__ out) {
    __shared__ float red[256];
    int tid = threadIdx.x;
    float s = 0.0f;
    for (int i = tid; i < 2 * NUM_SHELLS; i += 256) {
        int bt = i / NUM_SHELLS;
        int sh_ = i % NUM_SHELLS;
        const float* acc = g_acc + bt * 3 * NUM_SHELLS;
        float num = acc[sh_];
        float px  = acc[NUM_SHELLS + sh_];
        float py  = acc[2*NUM_SHELLS + sh_];
        s += num / sqrtf(px * py + 1e-8f);
    }
    red[tid] = s;
    __syncthreads();
    for (int o = 128; o > 0; o >>= 1) {
        if (tid < o) red[tid] += red[tid + o];
        __syncthreads();
    }
    if (tid == 0) out[0] = red[0] / (2.0f * NUM_SHELLS);
}

// ---------------------------------------------------------------------------
extern "C" void kernel_launch(void* const* d_in, const int* in_sizes, int n_in,
                              void* d_out, int out_size) {
    const float* X = (const float*)d_in[0];
    const float* Y = (const float*)d_in[1];

    cudaFuncSetAttribute(fft_z_reduce_kernel,
                         cudaFuncAttributeMaxDynamicSharedMemorySize,
                         (int)SMEM_Z);

    init_kernel<<<1, 256>>>();
    fft_x_kernel<<<8192, 256>>>(X, Y);              // 2 vols * 65536 lines / 16
    fft_y_kernel<<<8192, 256>>>();                  // 2 vols * 256 z * 16 tiles
    fft_z_reduce_kernel<<<2322, 1024, SMEM_Z>>>();  // 2 * 129 y * 9 x-tiles
    final_kernel<<<1, 256>>>((float*)d_out);
}

// round 15
// speedup vs baseline: 1.3234x; 1.0636x over previous
#include <cuda_runtime.h>
#include <cuda_fp16.h>
#include <math.h>

#define N_VOX (256*256*256)
#define NUM_SHELLS 222
#define NB (2*3*NUM_SHELLS)

// Hermitian-packed: 2 complex volumes (Z = X + iY per batch), two buffers,
// stored as half2 (re,im).
// g_F : [batch][z][y][x]   (after pass 1)
// g_F2: [batch][y][z][x]   (after pass 2; z becomes the stride-256 axis)
__device__ __half2 g_F [(size_t)2 * N_VOX];
__device__ __half2 g_F2[(size_t)2 * N_VOX];
__device__ float   g_acc[NB];
__device__ float2  g_tw[256];   // W256^k

__device__ __forceinline__ float2 cmulf(float2 a, float2 b) {
    return make_float2(a.x*b.x - a.y*b.y, a.x*b.y + a.y*b.x);
}
__device__ __forceinline__ __half2 f2h(float2 a) {
    return __floats2half2_rn(a.x, a.y);
}
__device__ __forceinline__ float2 h2f(__half2 a) {
    return __half22float2(a);
}

// ---------------------------------------------------------------------------
// 16-point radix-2 DIT FFT, fully specialized: trivial twiddles (1, -i) cost
// only adds/swaps; the rest are literal immediates (FFMA-imm, rt=1).
// Natural in -> natural out. Matches the generic loop version bit-exactly
// in structure (same butterfly order).
// ---------------------------------------------------------------------------
#define FFT_C1 0.92387953251128674f
#define FFT_S1 0.38268343236508977f
#define FFT_C2 0.70710678118654752f

// w = 1
#define BF1(i0,i1) { float2 a = v[i0], b = v[i1]; \
    v[i0] = make_float2(a.x + b.x, a.y + b.y); \
    v[i1] = make_float2(a.x - b.x, a.y - b.y); }
// w = -i : t = (b.y, -b.x)
#define BFJ(i0,i1) { float2 a = v[i0], b = v[i1]; \
    v[i0] = make_float2(a.x + b.y, a.y - b.x); \
    v[i1] = make_float2(a.x - b.y, a.y + b.x); }
// general literal twiddle (wr, wi)
#define BFW(i0,i1,wr,wi) { float2 a = v[i0], b = v[i1]; \
    float tr = b.x*(wr) - b.y*(wi); \
    float ti = b.x*(wi) + b.y*(wr); \
    v[i0] = make_float2(a.x + tr, a.y + ti); \
    v[i1] = make_float2(a.x - tr, a.y - ti); }

__device__ __forceinline__ void fft16(float2 v[16]) {
    float2 t;
#define SWP(a,b) { t = v[a]; v[a] = v[b]; v[b] = t; }
    SWP(1,8) SWP(2,4) SWP(3,12) SWP(5,10) SWP(7,14) SWP(11,13)
#undef SWP
    // stage 0 (half=1): all w = 1
    BF1(0,1) BF1(2,3) BF1(4,5) BF1(6,7)
    BF1(8,9) BF1(10,11) BF1(12,13) BF1(14,15)
    // stage 1 (half=2): w in {1, -i}
    BF1(0,2) BFJ(1,3)   BF1(4,6) BFJ(5,7)
    BF1(8,10) BFJ(9,11) BF1(12,14) BFJ(13,15)
    // stage 2 (half=4): w in {1, W16^2, -i, W16^6}
    BF1(0,4) BFW(1,5,  FFT_C2, -FFT_C2) BFJ(2,6) BFW(3,7,  -FFT_C2, -FFT_C2)
    BF1(8,12) BFW(9,13, FFT_C2, -FFT_C2) BFJ(10,14) BFW(11,15, -FFT_C2, -FFT_C2)
    // stage 3 (half=8): w = W16^pos, pos = 0..7
    BF1(0,8)
    BFW(1,9,   FFT_C1, -FFT_S1)
    BFW(2,10,  FFT_C2, -FFT_C2)
    BFW(3,11,  FFT_S1, -FFT_C1)
    BFJ(4,12)
    BFW(5,13, -FFT_S1, -FFT_C1)
    BFW(6,14, -FFT_C2, -FFT_C2)
    BFW(7,15, -FFT_C1, -FFT_S1)
}

// ---------------------------------------------------------------------------
__global__ void init_kernel() {
    int tid = threadIdx.x;
    for (int i = tid; i < NB; i += blockDim.x) g_acc[i] = 0.0f;
    if (tid < 256) {
        float ang = -6.283185307179586f * (float)tid / 256.0f;
        float s, c;
        sincosf(ang, &s, &c);
        g_tw[tid] = make_float2(c, s);
    }
}

// ---------------------------------------------------------------------------
// Pass 1: x-FFT of Z = X + iY (one complex volume per batch). fp32 in, fp16 out.
// ---------------------------------------------------------------------------
__global__ void __launch_bounds__(256)
fft_x_kernel(const float* __restrict__ X, const float* __restrict__ Y) {
    __shared__ float2 sh[16][16][17];
    __shared__ float2 tws[256];
    int tid = threadIdx.x;
    tws[tid] = g_tw[tid];
    int tt = tid & 15;
    int l  = tid >> 4;
    int line = blockIdx.x * 16 + l;       // 0 .. 131071
    int vol  = line >> 16;                // batch 0/1
    int lin  = line & 65535;
    const float* sx = X + (size_t)vol * N_VOX + (size_t)lin * 256;
    const float* sy = Y + (size_t)vol * N_VOX + (size_t)lin * 256;

    float2 v[16];
#pragma unroll
    for (int i = 0; i < 16; i++)
        v[i] = make_float2(sx[tt + 16*i], sy[tt + 16*i]);
    fft16(v);
    __syncthreads();
#pragma unroll
    for (int k2 = 1; k2 < 16; k2++)
        v[k2] = cmulf(v[k2], tws[tt * k2]);
#pragma unroll
    for (int k2 = 0; k2 < 16; k2++)
        sh[l][tt][k2] = v[k2];
    __syncthreads();
#pragma unroll
    for (int n1 = 0; n1 < 16; n1++)
        v[n1] = sh[l][n1][tt];
    fft16(v);
    __half2* dst = g_F + (size_t)vol * N_VOX + (size_t)lin * 256;
#pragma unroll
    for (int k1 = 0; k1 < 16; k1++)
        dst[tt + 16*k1] = f2h(v[k1]);
}

// ---------------------------------------------------------------------------
// Pass 2: y-FFT. Reads g_F [b][z][y][x] (stride-256 loads, half2),
// writes g_F2 [b][y][z][x] (strided stores, half2, fire-and-forget).
// ---------------------------------------------------------------------------
__global__ void __launch_bounds__(256)
fft_y_kernel() {
    __shared__ float2 sh[16][16][16];
    __shared__ float2 tws[256];
    int tid = threadIdx.x;
    tws[tid] = g_tw[tid];
    int c = tid & 15;
    int t = tid >> 4;
    int b    = blockIdx.x;
    int vol  = b >> 12;
    int rem  = b & 4095;
    int z    = rem >> 4;
    int tile = rem & 15;
    const __half2* srcv = g_F  + (size_t)vol * N_VOX + (size_t)z * 65536 + tile * 16;
    __half2*       dstv = g_F2 + (size_t)vol * N_VOX + (size_t)z * 256   + tile * 16;

    float2 v[16];
#pragma unroll
    for (int i = 0; i < 16; i++)
        v[i] = h2f(srcv[(size_t)(t + 16*i) * 256 + c]);
    fft16(v);
    __syncthreads();
#pragma unroll
    for (int k2 = 1; k2 < 16; k2++)
        v[k2] = cmulf(v[k2], tws[t * k2]);
#pragma unroll
    for (int k2 = 0; k2 < 16; k2++)
        sh[t][k2][c] = v[k2];
    __syncthreads();
#pragma unroll
    for (int n1 = 0; n1 < 16; n1++)
        v[n1] = sh[n1][t][c];
    fft16(v);
#pragma unroll
    for (int k1 = 0; k1 < 16; k1++)
        dstv[(size_t)(t + 16*k1) * 65536 + c] = f2h(v[k1]);
}

// ---------------------------------------------------------------------------
// Pass 3: 1024 threads. Quarter q FFTs column set q of
// {(x,y), (xm,y), (x,ym), (xm,ym)} and publishes its z-spectrum to shared.
// Then ALL quarters bin full +/- orbits — quarter q takes k1 in {2q, 2q+1}
// (8 voxels per orbit, merged in registers into ONE aggregated atomic head).
// Canonical cube x,y,z in 0..128. Block = (batch, y=0..128, x-tile of 16).
// Orbit-count coefficients (m* = 1 if coord in 1..127):
//   c1 = 1 + mx*my*mz   (V1 = f(x,y,z))
//   c2 = mx + my*mz     (V2 = f(xm,y,z))
//   c3 = my + mx*mz     (V3 = f(x,ym,z))
//   c4 = mz + mx*my     (V4 = f(xm,ym,z))
// Sum over cube of (c1+c2+c3+c4) = Prod(1+m) = 256^3 exactly.
// ---------------------------------------------------------------------------
#define SMEM_Z (4*4096*sizeof(float2) + 256*sizeof(float2) + 3*NUM_SHELLS*sizeof(float))

__device__ __forceinline__ void unpack3(float2 P, float2 Q,
                                        float& n, float& p, float& q_) {
    float xr = P.x + Q.x, xi = P.y - Q.y;   // 2*Fx
    float yr = P.y + Q.y, yi = Q.x - P.x;   // 2*Fy
    n  = xr*yr + xi*yi;
    p  = xr*xr + xi*xi;
    q_ = yr*yr + yi*yi;
}

__global__ void __launch_bounds__(1024, 1)
fft_z_reduce_kernel() {
    extern __shared__ unsigned char dynsm[];
    float2* shQ  = (float2*)dynsm;           // 4 buffers of 4096 float2
    float2* tws  = shQ + 4*4096;
    float*  bins = (float*)(tws + 256);

    int tid = threadIdx.x;
    if (tid < 256) tws[tid] = g_tw[tid];
    for (int i = tid; i < 3*NUM_SHELLS; i += 1024) bins[i] = 0.0f;

    int q  = tid >> 8;                   // quarter 0..3
    int wt = tid & 255;
    int c  = wt & 15;
    int t  = wt >> 4;
    int bI    = blockIdx.x;
    int batch = bI / 1161;               // 129*9
    int rem   = bI % 1161;
    int y     = rem / 9;                 // 0..128
    int tile  = rem % 9;                 // 0..8 (x = 0..143, masked > 128)
    int x  = tile * 16 + c;
    int xm = (256 - x) & 255;
    int ym = (256 - y) & 255;
    const __half2* base = g_F2 + (size_t)batch * N_VOX;

    int colx = (q & 1) ? xm : x;
    int coly = (q & 2) ? ym : y;
    float2* mySh = shQ + q * 4096;

    float2 v[16];
#pragma unroll
    for (int i = 0; i < 16; i++)
        v[i] = h2f(base[(size_t)coly * 65536 + (size_t)(t + 16*i) * 256 + colx]);
    fft16(v);
    __syncthreads();                     // #1: tws + bins ready
#pragma unroll
    for (int k2 = 1; k2 < 16; k2++)
        v[k2] = cmulf(v[k2], tws[t * k2]);
#pragma unroll
    for (int k2 = 0; k2 < 16; k2++)
        mySh[(t * 16 + k2) * 16 + c] = v[k2];
    __syncthreads();                     // #2: transpose ready
#pragma unroll
    for (int n1 = 0; n1 < 16; n1++)
        v[n1] = mySh[(n1 * 16 + t) * 16 + c];
    fft16(v);                            // v[k1] = Fz(col, z = t + 16*k1)
    __syncthreads();                     // #3: transpose reads done
    // publish z-layout: mySh[z*16 + c] = Fz(col, z)
#pragma unroll
    for (int k1 = 0; k1 < 16; k1++)
        mySh[(t + 16*k1) * 16 + c] = v[k1];
    __syncthreads();                     // #4: all four z-layouts ready

    // ---- orbit binning: ALL quarters participate; quarter q takes
    //      k1 = 2q + j, j in {0,1}. Reads only shared z-layouts. ----
    {
        const float2* shA = shQ;
        const float2* shB = shQ + 4096;
        const float2* shC = shQ + 8192;
        const float2* shD = shQ + 12288;

        float vx   = (x <= 128) ? 1.0f : 0.0f;
        float mx   = ((unsigned)(x - 1) < 127u) ? 1.0f : 0.0f;
        float my   = ((unsigned)(y - 1) < 127u) ? 1.0f : 0.0f;
        float mxmy = mx * my;
        int fx = (x <= 128) ? x : 256 - x;   // keep bin in range for dead x
        int rxy = fx*fx + y*y;               // y canonical: fy = y

        const unsigned FULL = 0xffffffffu;
        int lpos = tid & 15;

#pragma unroll
        for (int j = 0; j < 2; j++) {
            int k1  = 2*q + j;
            int z   = t + 16*k1;             // 0..127 (covered once across quarters)
            int zmw = (256 - z) & 255;       // partner plane (z=0 -> 0)
            float mz = (z >= 1) ? 1.0f : 0.0f;
            float c1 = vx * (1.0f + mxmy * mz);
            float c2 = vx * (mx + my * mz);
            float c3 = vx * (my + mx * mz);
            float c4 = vx * (mz + mxmy);

            int zi = z * 16 + c, zmi = zmw * 16 + c;
            float n1,p1,q1, n2,p2,q2, n3,p3,q3, n4,p4,q4;
            unpack3(shA[zi],  shD[zmi], n1, p1, q1);   // V1 = f(x,y,z)
            unpack3(shB[zi],  shC[zmi], n2, p2, q2);   // V2 = f(xm,y,z)
            unpack3(shC[zi],  shB[zmi], n3, p3, q3);   // V3 = f(x,ym,z)
            unpack3(shD[zi],  shA[zmi], n4, p4, q4);   // V4 = f(xm,ym,z)

            int bin = (int)sqrtf((float)(rxy + z*z));
            float nn = c1*n1 + c2*n2 + c3*n3 + c4*n4;
            float pp = c1*p1 + c2*p2 + c3*p3 + c4*p4;
            float qq = c1*q1 + c2*q2 + c3*q3 + c4*q4;

            // run-aggregation within each 16-lane segment (bin monotone in x)
#pragma unroll
            for (int off = 1; off < 16; off <<= 1) {
                int   ob = __shfl_down_sync(FULL, bin, off);
                float on = __shfl_down_sync(FULL, nn,  off);
                float op = __shfl_down_sync(FULL, pp,  off);
                float oq = __shfl_down_sync(FULL, qq,  off);
                if (lpos + off < 16 && ob == bin) { nn += on; pp += op; qq += oq; }
            }
            int pb = __shfl_up_sync(FULL, bin, 1);
            if (lpos == 0 || pb != bin) {
                atomicAdd(&bins[bin],                nn);
                atomicAdd(&bins[NUM_SHELLS   + bin], pp);
                atomicAdd(&bins[2*NUM_SHELLS + bin], qq);
            }
        }

        // z = 128 plane (self-partner): quarter 0, t==0 segment only.
        if (q == 0 && t == 0) {
            const unsigned M16 = 0x0000ffffu;
            int zi = 128 * 16 + c;
            float c1 = vx * 1.0f;
            float c2 = vx * mx;
            float c3 = vx * my;
            float c4 = vx * mxmy;
            float n1,p1,q1, n2,p2,q2, n3,p3,q3, n4,p4,q4;
            unpack3(shA[zi], shD[zi], n1, p1, q1);
            unpack3(shB[zi], shC[zi], n2, p2, q2);
            unpack3(shC[zi], shB[zi], n3, p3, q3);
            unpack3(shD[zi], shA[zi], n4, p4, q4);
            int bin = (int)sqrtf((float)(rxy + 16384));
            float nn = c1*n1 + c2*n2 + c3*n3 + c4*n4;
            float pp = c1*p1 + c2*p2 + c3*p3 + c4*p4;
            float qq = c1*q1 + c2*q2 + c3*q3 + c4*q4;
#pragma unroll
            for (int off = 1; off < 16; off <<= 1) {
                int   ob = __shfl_down_sync(M16, bin, off);
                float on = __shfl_down_sync(M16, nn,  off);
                float op = __shfl_down_sync(M16, pp,  off);
                float oq = __shfl_down_sync(M16, qq,  off);
                if (lpos + off < 16 && ob == bin) { nn += on; pp += op; qq += oq; }
            }
            int pb = __shfl_up_sync(M16, bin, 1);
            if (lpos == 0 || pb != bin) {
                atomicAdd(&bins[bin],                nn);
                atomicAdd(&bins[NUM_SHELLS   + bin], pp);
                atomicAdd(&bins[2*NUM_SHELLS + bin], qq);
            }
        }
    }
    __syncthreads();                     // #5: bins complete
    float* acc = g_acc + batch * 3 * NUM_SHELLS;
    for (int i = tid; i < 3 * NUM_SHELLS; i += 1024)
        atomicAdd(&acc[i], bins[i]);
}

// ---------------------------------------------------------------------------
__global__ void final_kernel(float* __restrict__ out) {
    __shared__ float red[256];
    int tid = threadIdx.x;
    float s = 0.0f;
    for (int i = tid; i < 2 * NUM_SHELLS; i += 256) {
        int bt = i / NUM_SHELLS;
        int sh_ = i % NUM_SHELLS;
        const float* acc = g_acc + bt * 3 * NUM_SHELLS;
        float num = acc[sh_];
        float px  = acc[NUM_SHELLS + sh_];
        float py  = acc[2*NUM_SHELLS + sh_];
        s += num / sqrtf(px * py + 1e-8f);
    }
    red[tid] = s;
    __syncthreads();
    for (int o = 128; o > 0; o >>= 1) {
        if (tid < o) red[tid] += red[tid + o];
        __syncthreads();
    }
    if (tid == 0) out[0] = red[0] / (2.0f * NUM_SHELLS);
}

// ---------------------------------------------------------------------------
extern "C" void kernel_launch(void* const* d_in, const int* in_sizes, int n_in,
                              void* d_out, int out_size) {
    const float* X = (const float*)d_in[0];
    const float* Y = (const float*)d_in[1];

    cudaFuncSetAttribute(fft_z_reduce_kernel,
                         cudaFuncAttributeMaxDynamicSharedMemorySize,
                         (int)SMEM_Z);

    init_kernel<<<1, 256>>>();
    fft_x_kernel<<<8192, 256>>>(X, Y);              // 2 vols * 65536 lines / 16
    fft_y_kernel<<<8192, 256>>>();                  // 2 vols * 256 z * 16 tiles
    fft_z_reduce_kernel<<<2322, 1024, SMEM_Z>>>();  // 2 * 129 y * 9 x-tiles
    final_kernel<<<1, 256>>>((float*)d_out);
}

// round 17
// speedup vs baseline: 1.5154x; 1.1451x over previous
#include <cuda_runtime.h>
#include <cuda_fp16.h>
#include <math.h>

#define N_VOX (256*256*256)
#define NUM_SHELLS 222
#define NB (2*3*NUM_SHELLS)

// Hermitian-packed: 2 complex volumes (Z = X + iY per batch), two buffers,
// stored as half2 (re,im).
// g_F : [batch][z][y][x]   (after pass 1)
// g_F2: [batch][y][z][x]   (after pass 2; z becomes the stride-256 axis)
__device__ __half2 g_F [(size_t)2 * N_VOX];
__device__ __half2 g_F2[(size_t)2 * N_VOX];
__device__ float   g_acc[NB];
__device__ float2  g_tw[256];   // W256^k

__device__ __forceinline__ float2 cmulf(float2 a, float2 b) {
    return make_float2(a.x*b.x - a.y*b.y, a.x*b.y + a.y*b.x);
}
__device__ __forceinline__ __half2 f2h(float2 a) {
    return __floats2half2_rn(a.x, a.y);
}
__device__ __forceinline__ float2 h2f(__half2 a) {
    return __half22float2(a);
}

// ---------------------------------------------------------------------------
// 16-point radix-2 DIT FFT, fully specialized: trivial twiddles (1, -i) cost
// only adds/swaps; the rest are literal immediates. Natural in -> natural out.
// ---------------------------------------------------------------------------
#define FFT_C1 0.92387953251128674f
#define FFT_S1 0.38268343236508977f
#define FFT_C2 0.70710678118654752f

#define BF1(i0,i1) { float2 a = v[i0], b = v[i1]; \
    v[i0] = make_float2(a.x + b.x, a.y + b.y); \
    v[i1] = make_float2(a.x - b.x, a.y - b.y); }
#define BFJ(i0,i1) { float2 a = v[i0], b = v[i1]; \
    v[i0] = make_float2(a.x + b.y, a.y - b.x); \
    v[i1] = make_float2(a.x - b.y, a.y + b.x); }
#define BFW(i0,i1,wr,wi) { float2 a = v[i0], b = v[i1]; \
    float tr = b.x*(wr) - b.y*(wi); \
    float ti = b.x*(wi) + b.y*(wr); \
    v[i0] = make_float2(a.x + tr, a.y + ti); \
    v[i1] = make_float2(a.x - tr, a.y - ti); }

__device__ __forceinline__ void fft16(float2 v[16]) {
    float2 t;
#define SWP(a,b) { t = v[a]; v[a] = v[b]; v[b] = t; }
    SWP(1,8) SWP(2,4) SWP(3,12) SWP(5,10) SWP(7,14) SWP(11,13)
#undef SWP
    BF1(0,1) BF1(2,3) BF1(4,5) BF1(6,7)
    BF1(8,9) BF1(10,11) BF1(12,13) BF1(14,15)
    BF1(0,2) BFJ(1,3)   BF1(4,6) BFJ(5,7)
    BF1(8,10) BFJ(9,11) BF1(12,14) BFJ(13,15)
    BF1(0,4) BFW(1,5,  FFT_C2, -FFT_C2) BFJ(2,6) BFW(3,7,  -FFT_C2, -FFT_C2)
    BF1(8,12) BFW(9,13, FFT_C2, -FFT_C2) BFJ(10,14) BFW(11,15, -FFT_C2, -FFT_C2)
    BF1(0,8)
    BFW(1,9,   FFT_C1, -FFT_S1)
    BFW(2,10,  FFT_C2, -FFT_C2)
    BFW(3,11,  FFT_S1, -FFT_C1)
    BFJ(4,12)
    BFW(5,13, -FFT_S1, -FFT_C1)
    BFW(6,14, -FFT_C2, -FFT_C2)
    BFW(7,15, -FFT_C1, -FFT_S1)
}

// ---------------------------------------------------------------------------
__global__ void init_kernel() {
    int tid = threadIdx.x;
    for (int i = tid; i < NB; i += blockDim.x) g_acc[i] = 0.0f;
    if (tid < 256) {
        float ang = -6.283185307179586f * (float)tid / 256.0f;
        float s, c;
        sincosf(ang, &s, &c);
        g_tw[tid] = make_float2(c, s);
    }
}

// ---------------------------------------------------------------------------
// Pass 1: x-FFT of Z = X + iY (one complex volume per batch). fp32 in, fp16 out.
// ---------------------------------------------------------------------------
__global__ void __launch_bounds__(256)
fft_x_kernel(const float* __restrict__ X, const float* __restrict__ Y) {
    __shared__ float2 sh[16][16][17];
    __shared__ float2 tws[256];
    int tid = threadIdx.x;
    tws[tid] = g_tw[tid];
    int tt = tid & 15;
    int l  = tid >> 4;
    int line = blockIdx.x * 16 + l;       // 0 .. 131071
    int vol  = line >> 16;                // batch 0/1
    int lin  = line & 65535;
    const float* sx = X + (size_t)vol * N_VOX + (size_t)lin * 256;
    const float* sy = Y + (size_t)vol * N_VOX + (size_t)lin * 256;

    float2 v[16];
#pragma unroll
    for (int i = 0; i < 16; i++)
        v[i] = make_float2(sx[tt + 16*i], sy[tt + 16*i]);
    fft16(v);
    __syncthreads();
#pragma unroll
    for (int k2 = 1; k2 < 16; k2++)
        v[k2] = cmulf(v[k2], tws[tt * k2]);
#pragma unroll
    for (int k2 = 0; k2 < 16; k2++)
        sh[l][tt][k2] = v[k2];
    __syncthreads();
#pragma unroll
    for (int n1 = 0; n1 < 16; n1++)
        v[n1] = sh[l][n1][tt];
    fft16(v);
    __half2* dst = g_F + (size_t)vol * N_VOX + (size_t)lin * 256;
#pragma unroll
    for (int k1 = 0; k1 < 16; k1++)
        dst[tt + 16*k1] = f2h(v[k1]);
}

// ---------------------------------------------------------------------------
// Pass 2: y-FFT. Reads g_F [b][z][y][x] (stride-256 loads, half2),
// writes g_F2 [b][y][z][x] (strided stores, half2, fire-and-forget).
// ---------------------------------------------------------------------------
__global__ void __launch_bounds__(256)
fft_y_kernel() {
    __shared__ float2 sh[16][16][16];
    __shared__ float2 tws[256];
    int tid = threadIdx.x;
    tws[tid] = g_tw[tid];
    int c = tid & 15;
    int t = tid >> 4;
    int b    = blockIdx.x;
    int vol  = b >> 12;
    int rem  = b & 4095;
    int z    = rem >> 4;
    int tile = rem & 15;
    const __half2* srcv = g_F  + (size_t)vol * N_VOX + (size_t)z * 65536 + tile * 16;
    __half2*       dstv = g_F2 + (size_t)vol * N_VOX + (size_t)z * 256   + tile * 16;

    float2 v[16];
#pragma unroll
    for (int i = 0; i < 16; i++)
        v[i] = h2f(srcv[(size_t)(t + 16*i) * 256 + c]);
    fft16(v);
    __syncthreads();
#pragma unroll
    for (int k2 = 1; k2 < 16; k2++)
        v[k2] = cmulf(v[k2], tws[t * k2]);
#pragma unroll
    for (int k2 = 0; k2 < 16; k2++)
        sh[t][k2][c] = v[k2];
    __syncthreads();
#pragma unroll
    for (int n1 = 0; n1 < 16; n1++)
        v[n1] = sh[n1][t][c];
    fft16(v);
#pragma unroll
    for (int k1 = 0; k1 < 16; k1++)
        dstv[(size_t)(t + 16*k1) * 65536 + c] = f2h(v[k1]);
}

// ---------------------------------------------------------------------------
// Pass 3: 512 threads, 2 CTAs/SM. Half h serially z-FFTs two column sets:
//   h=0: (x,y)  -> spec[0], then (x,ym)  -> spec[2]
//   h=1: (xm,y) -> spec[1], then (xm,ym) -> spec[3]
// Spectra stored in shared as half2 (z-layout: spec[q][z*16+c] = Fz(col_q,z)).
// Then all threads bin full +/- orbits; half h takes k1 = 4h+j, j=0..3.
// Canonical cube x,y,z in 0..128. Block = (batch, y=0..128, x-tile of 16).
// Orbit-count coefficients (m* = 1 if coord in 1..127):
//   c1 = 1 + mx*my*mz (V1=f(x,y,z))   c2 = mx + my*mz (V2=f(xm,y,z))
//   c3 = my + mx*mz   (V3=f(x,ym,z))  c4 = mz + mx*my (V4=f(xm,ym,z))
// ---------------------------------------------------------------------------
#define SMEM_Z (4*4096*sizeof(__half2) + 256*sizeof(float2) + 3*NUM_SHELLS*sizeof(float))

__device__ __forceinline__ void unpack3(float2 P, float2 Q,
                                        float& n, float& p, float& q_) {
    float xr = P.x + Q.x, xi = P.y - Q.y;   // 2*Fx
    float yr = P.y + Q.y, yi = Q.x - P.x;   // 2*Fy
    n  = xr*yr + xi*yi;
    p  = xr*xr + xi*xi;
    q_ = yr*yr + yi*yi;
}

__global__ void __launch_bounds__(512, 2)
fft_z_reduce_kernel() {
    extern __shared__ unsigned char dynsm[];
    __half2* spec = (__half2*)dynsm;             // 4 buffers of 4096 half2
    float2*  tws  = (float2*)(spec + 4*4096);
    float*   bins = (float*)(tws + 256);

    int tid = threadIdx.x;
    if (tid < 256) tws[tid] = g_tw[tid];
    for (int i = tid; i < 3*NUM_SHELLS; i += 512) bins[i] = 0.0f;

    int h  = tid >> 8;                   // half 0/1
    int wt = tid & 255;
    int c  = wt & 15;
    int t  = wt >> 4;
    int bI    = blockIdx.x;
    int batch = bI / 1161;               // 129*9
    int rem   = bI % 1161;
    int y     = rem / 9;                 // 0..128
    int tile  = rem % 9;                 // 0..8 (x = 0..143, masked > 128)
    int x  = tile * 16 + c;
    int xm = (256 - x) & 255;
    int ym = (256 - y) & 255;
    const __half2* base = g_F2 + (size_t)batch * N_VOX;

    int colx = h ? xm : x;
    __half2* b0 = spec + h * 4096;           // pass-0 buffer (q = h)
    __half2* b1 = spec + (2 + h) * 4096;     // pass-1 buffer (q = 2+h)

    float2 v[16];

    // ======== pass 0: coly = y ========
#pragma unroll
    for (int i = 0; i < 16; i++)
        v[i] = h2f(base[(size_t)y * 65536 + (size_t)(t + 16*i) * 256 + colx]);
    fft16(v);
    __syncthreads();                     // #1: tws + bins ready
#pragma unroll
    for (int k2 = 1; k2 < 16; k2++)
        v[k2] = cmulf(v[k2], tws[t * k2]);
#pragma unroll
    for (int k2 = 0; k2 < 16; k2++)
        b0[(t * 16 + k2) * 16 + c] = f2h(v[k2]);
    __syncthreads();                     // #2: transpose ready
#pragma unroll
    for (int n1 = 0; n1 < 16; n1++)
        v[n1] = h2f(b0[(n1 * 16 + t) * 16 + c]);
    fft16(v);
    __syncthreads();                     // #3: transpose reads done
#pragma unroll
    for (int k1 = 0; k1 < 16; k1++)
        b0[(t + 16*k1) * 16 + c] = f2h(v[k1]);   // z-layout

    // ======== pass 1: coly = ym ========
#pragma unroll
    for (int i = 0; i < 16; i++)
        v[i] = h2f(base[(size_t)ym * 65536 + (size_t)(t + 16*i) * 256 + colx]);
    fft16(v);
#pragma unroll
    for (int k2 = 1; k2 < 16; k2++)
        v[k2] = cmulf(v[k2], tws[t * k2]);
#pragma unroll
    for (int k2 = 0; k2 < 16; k2++)
        b1[(t * 16 + k2) * 16 + c] = f2h(v[k2]);
    __syncthreads();                     // #4: transpose ready
#pragma unroll
    for (int n1 = 0; n1 < 16; n1++)
        v[n1] = h2f(b1[(n1 * 16 + t) * 16 + c]);
    fft16(v);
    __syncthreads();                     // #5: transpose reads done
#pragma unroll
    for (int k1 = 0; k1 < 16; k1++)
        b1[(t + 16*k1) * 16 + c] = f2h(v[k1]);
    __syncthreads();                     // #6: all four z-layouts ready

    // ======== orbit binning: half h takes k1 = 4h + j, j = 0..3 ========
    {
        const __half2* sA = spec;
        const __half2* sB = spec + 4096;
        const __half2* sC = spec + 8192;
        const __half2* sD = spec + 12288;

        float vx   = (x <= 128) ? 1.0f : 0.0f;
        float mx   = ((unsigned)(x - 1) < 127u) ? 1.0f : 0.0f;
        float my   = ((unsigned)(y - 1) < 127u) ? 1.0f : 0.0f;
        float mxmy = mx * my;
        int fx = (x <= 128) ? x : 256 - x;   // keep bin in range for dead x
        int rxy = fx*fx + y*y;               // y canonical: fy = y

        const unsigned FULL = 0xffffffffu;
        int lpos = tid & 15;

#pragma unroll
        for (int j = 0; j < 4; j++) {
            int k1  = 4*h + j;
            int z   = t + 16*k1;             // 0..127 across both halves
            int zmw = (256 - z) & 255;       // partner plane (z=0 -> 0)
            float mz = (z >= 1) ? 1.0f : 0.0f;
            float c1 = vx * (1.0f + mxmy * mz);
            float c2 = vx * (mx + my * mz);
            float c3 = vx * (my + mx * mz);
            float c4 = vx * (mz + mxmy);

            int zi = z * 16 + c, zmi = zmw * 16 + c;
            float n1,p1,q1, n2,p2,q2, n3,p3,q3, n4,p4,q4;
            unpack3(h2f(sA[zi]), h2f(sD[zmi]), n1, p1, q1);   // V1 = f(x,y,z)
            unpack3(h2f(sB[zi]), h2f(sC[zmi]), n2, p2, q2);   // V2 = f(xm,y,z)
            unpack3(h2f(sC[zi]), h2f(sB[zmi]), n3, p3, q3);   // V3 = f(x,ym,z)
            unpack3(h2f(sD[zi]), h2f(sA[zmi]), n4, p4, q4);   // V4 = f(xm,ym,z)

            int bin = (int)sqrtf((float)(rxy + z*z));
            float nn = c1*n1 + c2*n2 + c3*n3 + c4*n4;
            float pp = c1*p1 + c2*p2 + c3*p3 + c4*p4;
            float qq = c1*q1 + c2*q2 + c3*q3 + c4*q4;

            // run-aggregation within each 16-lane segment (bin monotone in x)
#pragma unroll
            for (int off = 1; off < 16; off <<= 1) {
                int   ob = __shfl_down_sync(FULL, bin, off);
                float on = __shfl_down_sync(FULL, nn,  off);
                float op = __shfl_down_sync(FULL, pp,  off);
                float oq = __shfl_down_sync(FULL, qq,  off);
                if (lpos + off < 16 && ob == bin) { nn += on; pp += op; qq += oq; }
            }
            int pb = __shfl_up_sync(FULL, bin, 1);
            if (lpos == 0 || pb != bin) {
                atomicAdd(&bins[bin],                nn);
                atomicAdd(&bins[NUM_SHELLS   + bin], pp);
                atomicAdd(&bins[2*NUM_SHELLS + bin], qq);
            }
        }

        // z = 128 plane (self-partner): half 0, t==0 segment only.
        if (h == 0 && t == 0) {
            const unsigned M16 = 0x0000ffffu;
            int zi = 128 * 16 + c;
            float c1 = vx * 1.0f;
            float c2 = vx * mx;
            float c3 = vx * my;
            float c4 = vx * mxmy;
            float n1,p1,q1, n2,p2,q2, n3,p3,q3, n4,p4,q4;
            unpack3(h2f(sA[zi]), h2f(sD[zi]), n1, p1, q1);
            unpack3(h2f(sB[zi]), h2f(sC[zi]), n2, p2, q2);
            unpack3(h2f(sC[zi]), h2f(sB[zi]), n3, p3, q3);
            unpack3(h2f(sD[zi]), h2f(sA[zi]), n4, p4, q4);
            int bin = (int)sqrtf((float)(rxy + 16384));
            float nn = c1*n1 + c2*n2 + c3*n3 + c4*n4;
            float pp = c1*p1 + c2*p2 + c3*p3 + c4*p4;
            float qq = c1*q1 + c2*q2 + c3*q3 + c4*q4;
#pragma unroll
            for (int off = 1; off < 16; off <<= 1) {
                int   ob = __shfl_down_sync(M16, bin, off);
                float on = __shfl_down_sync(M16, nn,  off);
                float op = __shfl_down_sync(M16, pp,  off);
                float oq = __shfl_down_sync(M16, qq,  off);
                if (lpos + off < 16 && ob == bin) { nn += on; pp += op; qq += oq; }
            }
            int pb = __shfl_up_sync(M16, bin, 1);
            if (lpos == 0 || pb != bin) {
                atomicAdd(&bins[bin],                nn);
                atomicAdd(&bins[NUM_SHELLS   + bin], pp);
                atomicAdd(&bins[2*NUM_SHELLS + bin], qq);
            }
        }
    }
    __syncthreads();                     // #7: bins complete
    float* acc = g_acc + batch * 3 * NUM_SHELLS;
    for (int i = tid; i < 3 * NUM_SHELLS; i += 512)
        atomicAdd(&acc[i], bins[i]);
}

// ---------------------------------------------------------------------------
__global__ void final_kernel(float* __restrict__ out) {
    __shared__ float red[256];
    int tid = threadIdx.x;
    float s = 0.0f;
    for (int i = tid; i < 2 * NUM_SHELLS; i += 256) {
        int bt = i / NUM_SHELLS;
        int sh_ = i % NUM_SHELLS;
        const float* acc = g_acc + bt * 3 * NUM_SHELLS;
        float num = acc[sh_];
        float px  = acc[NUM_SHELLS + sh_];
        float py  = acc[2*NUM_SHELLS + sh_];
        s += num / sqrtf(px * py + 1e-8f);
    }
    red[tid] = s;
    __syncthreads();
    for (int o = 128; o > 0; o >>= 1) {
        if (tid < o) red[tid] += red[tid + o];
        __syncthreads();
    }
    if (tid == 0) out[0] = red[0] / (2.0f * NUM_SHELLS);
}

// ---------------------------------------------------------------------------
extern "C" void kernel_launch(void* const* d_in, const int* in_sizes, int n_in,
                              void* d_out, int out_size) {
    const float* X = (const float*)d_in[0];
    const float* Y = (const float*)d_in[1];

    cudaFuncSetAttribute(fft_z_reduce_kernel,
                         cudaFuncAttributeMaxDynamicSharedMemorySize,
                         (int)SMEM_Z);

    init_kernel<<<1, 256>>>();
    fft_x_kernel<<<8192, 256>>>(X, Y);              // 2 vols * 65536 lines / 16
    fft_y_kernel<<<8192, 256>>>();                  // 2 vols * 256 z * 16 tiles
    fft_z_reduce_kernel<<<2322, 512, SMEM_Z>>>();   // 2 * 129 y * 9 x-tiles
    final_kernel<<<1, 256>>>((float*)d_out);
}